// round 1
// baseline (speedup 1.0000x reference)
#include <cuda_runtime.h>

#define MULC 32
#define NODE_ROW 128          // 4*MUL floats per node
#define OUT_ROW 256           // output floats per node
#define TABLE_N 8192
#define XMIN (-8.0f)
#define XMAX (8.0f)
#define INV_SQRT3 0.57735026918962576f
#define OUT_SCALE 0.25f       // 1/sqrt(16)

// Lookup table for mix(ea0): TABLE_N rows x 128 cols. Static device scratch (no allocs).
__device__ float g_mix_table[TABLE_N * 128];

// ---------------------------------------------------------------------------
// Kernel 1: build mix(x) table. One block (128 threads) per grid point.
//   h0 = swish(x * w0)            (64)
//   h1 = swish(h0 @ w1 * 0.125)   (64)
//   mix = h1 @ w2 * 0.125         (128)
// Folds: *0.25 global scale; cols [32,64) *= INV_SQRT3 (tp_0e factor).
// ---------------------------------------------------------------------------
__global__ void build_table_kernel(const float* __restrict__ w0,
                                   const float* __restrict__ w1,
                                   const float* __restrict__ w2) {
    __shared__ float h0[64];
    __shared__ float h1[64];
    const int t = threadIdx.x;                     // 0..127
    const float dx = (XMAX - XMIN) / (float)(TABLE_N - 1);
    const float x = XMIN + dx * (float)blockIdx.x;

    if (t < 64) {
        float z = x * w0[t];
        h0[t] = z / (1.0f + expf(-z));
    }
    __syncthreads();
    if (t < 64) {
        float acc = 0.0f;
#pragma unroll 8
        for (int i = 0; i < 64; i++) acc = fmaf(h0[i], w1[i * 64 + t], acc);
        float z = acc * 0.125f;
        h1[t] = z / (1.0f + expf(-z));
    }
    __syncthreads();
    {
        float acc = 0.0f;
#pragma unroll 8
        for (int i = 0; i < 64; i++) acc = fmaf(h1[i], w2[i * 128 + t], acc);
        float m = acc * 0.125f * OUT_SCALE;
        if (t >= 32 && t < 64) m *= INV_SQRT3;     // tp_0e normalization folded in
        g_mix_table[blockIdx.x * 128 + t] = m;
    }
}

// ---------------------------------------------------------------------------
// Kernel 2: per-edge message + scatter. One warp per edge.
// Lane l owns channel c=l:
//   s_e      = node[l]
//   v_e[i]   = node[32+3l+i]
//   mix cols l, 32+l, 64+l, 96+l  (lerp from table)
// Produces msg[256]:
//   msg[l]        = s_e * mix[l]
//   msg[32+l]     = dot(v_e, ea1) * mix[32+l]      (INV_SQRT3 folded in table)
//   msg[64+3l+i]  = v_e[i] * mix[64+l]
//   msg[160+3l+i] = s_e * ea1[i] * mix[96+l]
// Shared transpose to contiguous per-lane 8-float chunks, then 2x red.v4.f32.
// ---------------------------------------------------------------------------
__global__ void edge_kernel(const float* __restrict__ node_feats,
                            const float4* __restrict__ edge_attrs,
                            const int* __restrict__ senders,
                            const int* __restrict__ receivers,
                            float* __restrict__ out,
                            int E) {
    __shared__ float sh[8][OUT_ROW];               // 8 warps x 256 floats = 8 KB
    const int wid  = threadIdx.x >> 5;
    const int lane = threadIdx.x & 31;
    const int e = blockIdx.x * 8 + wid;
    if (e >= E) return;

    const int s = __ldg(&senders[e]);
    const int r = __ldg(&receivers[e]);
    const float4 ea = __ldg(&edge_attrs[e]);       // ea.x = ea0; (y,z,w) = ea1

    // Gather node feats for this lane's channel
    const float* nrow = node_feats + (size_t)s * NODE_ROW;
    const float s_e = __ldg(nrow + lane);
    const float v0  = __ldg(nrow + 32 + 3 * lane);
    const float v1  = __ldg(nrow + 33 + 3 * lane);
    const float v2  = __ldg(nrow + 34 + 3 * lane);

    // mix lookup (lerp)
    const float inv_dx = (float)(TABLE_N - 1) / (XMAX - XMIN);
    float t = (ea.x - XMIN) * inv_dx;
    t = fminf(fmaxf(t, 0.0f), (float)(TABLE_N - 1) - 1.0e-3f);
    const int i0 = (int)t;
    const float f = t - (float)i0;
    const float* row0 = g_mix_table + (size_t)i0 * 128;
    const float* row1 = row0 + 128;

    float m_s, m_t, m_v, m_p;
    {
        float a, b;
        a = __ldg(row0 + lane);       b = __ldg(row1 + lane);       m_s = fmaf(b - a, f, a);
        a = __ldg(row0 + 32 + lane);  b = __ldg(row1 + 32 + lane);  m_t = fmaf(b - a, f, a);
        a = __ldg(row0 + 64 + lane);  b = __ldg(row1 + 64 + lane);  m_v = fmaf(b - a, f, a);
        a = __ldg(row0 + 96 + lane);  b = __ldg(row1 + 96 + lane);  m_p = fmaf(b - a, f, a);
    }

    // Compute message values for this channel
    const float msg_s  = s_e * m_s;
    const float dot3   = fmaf(v0, ea.y, fmaf(v1, ea.z, v2 * ea.w));
    const float msg_t  = dot3 * m_t;               // INV_SQRT3 already folded in
    const float mv0 = v0 * m_v, mv1 = v1 * m_v, mv2 = v2 * m_v;
    const float sp  = s_e * m_p;
    const float mp0 = sp * ea.y, mp1 = sp * ea.z, mp2 = sp * ea.w;

    // Transpose via shared (stride-3 stores are bank-conflict free)
    float* shw = sh[wid];
    shw[lane]            = msg_s;
    shw[32 + lane]       = msg_t;
    shw[64  + 3 * lane]     = mv0;
    shw[64  + 3 * lane + 1] = mv1;
    shw[64  + 3 * lane + 2] = mv2;
    shw[160 + 3 * lane]     = mp0;
    shw[160 + 3 * lane + 1] = mp1;
    shw[160 + 3 * lane + 2] = mp2;
    __syncwarp();

    const float4 o0 = *(const float4*)&shw[8 * lane];
    const float4 o1 = *(const float4*)&shw[8 * lane + 4];

    float* op = out + (size_t)r * OUT_ROW + 8 * lane;
    asm volatile("red.global.add.v4.f32 [%0], {%1,%2,%3,%4};"
                 :: "l"(op), "f"(o0.x), "f"(o0.y), "f"(o0.z), "f"(o0.w) : "memory");
    asm volatile("red.global.add.v4.f32 [%0], {%1,%2,%3,%4};"
                 :: "l"(op + 4), "f"(o1.x), "f"(o1.y), "f"(o1.z), "f"(o1.w) : "memory");
}

// ---------------------------------------------------------------------------
// Launch
// inputs: 0 node_feats (50000x128 f32), 1 edge_attrs (800000x4 f32),
//         2 senders (int32), 3 receivers (int32),
//         4 w_mlp0 (1x64), 5 w_mlp1 (64x64), 6 w_mlp2 (64x128)
// output: 50000x256 f32
// ---------------------------------------------------------------------------
extern "C" void kernel_launch(void* const* d_in, const int* in_sizes, int n_in,
                              void* d_out, int out_size) {
    const float* node_feats = (const float*)d_in[0];
    const float* edge_attrs = (const float*)d_in[1];
    const int*   senders    = (const int*)d_in[2];
    const int*   receivers  = (const int*)d_in[3];
    const float* w0         = (const float*)d_in[4];
    const float* w1         = (const float*)d_in[5];
    const float* w2         = (const float*)d_in[6];
    float* out = (float*)d_out;
    const int E = in_sizes[1] / 4;   // edge_attrs is E x 4

    cudaMemsetAsync(d_out, 0, (size_t)out_size * sizeof(float));
    build_table_kernel<<<TABLE_N, 128>>>(w0, w1, w2);
    edge_kernel<<<(E + 7) / 8, 256>>>(node_feats, (const float4*)edge_attrs,
                                      senders, receivers, out, E);
}

// round 2
// speedup vs baseline: 1.4011x; 1.4011x over previous
#include <cuda_runtime.h>

#define N_NODES_MAX 50000
#define N_EDGES_MAX 800000
#define NODE_ROW 128          // 4*MUL floats per node
#define OUT_ROW 256           // output floats per node
#define TABLE_N 512
#define XMIN (-8.0f)
#define XMAX (8.0f)
#define INV_SQRT3 0.57735026918962576f
#define OUT_SCALE 0.25f       // 1/sqrt(16)

// ---- static device scratch (no allocations allowed) ----
__device__ float g_mix_table[TABLE_N * 128];       // 256 KB, mostly L1-resident
__device__ int   g_counts[N_NODES_MAX];
__device__ int   g_rowptr[N_NODES_MAX + 1];
__device__ int   g_cursor[N_NODES_MAX];
__device__ int   g_eids[N_EDGES_MAX];

// ---------------------------------------------------------------------------
// Kernel 1: build mix(x) table. One block (128 threads) per grid point.
// Folds: *0.25 global scale; cols [32,64) *= INV_SQRT3 (tp_0e factor).
// ---------------------------------------------------------------------------
__global__ void build_table_kernel(const float* __restrict__ w0,
                                   const float* __restrict__ w1,
                                   const float* __restrict__ w2) {
    __shared__ float h0[64];
    __shared__ float h1[64];
    const int t = threadIdx.x;                     // 0..127
    const float dx = (XMAX - XMIN) / (float)(TABLE_N - 1);
    const float x = XMIN + dx * (float)blockIdx.x;

    if (t < 64) {
        float z = x * w0[t];
        h0[t] = z / (1.0f + expf(-z));
    }
    __syncthreads();
    if (t < 64) {
        float acc = 0.0f;
#pragma unroll 8
        for (int i = 0; i < 64; i++) acc = fmaf(h0[i], w1[i * 64 + t], acc);
        float z = acc * 0.125f;
        h1[t] = z / (1.0f + expf(-z));
    }
    __syncthreads();
    {
        float acc = 0.0f;
#pragma unroll 8
        for (int i = 0; i < 64; i++) acc = fmaf(h1[i], w2[i * 128 + t], acc);
        float m = acc * 0.125f * OUT_SCALE;
        if (t >= 32 && t < 64) m *= INV_SQRT3;     // tp_0e normalization folded in
        g_mix_table[blockIdx.x * 128 + t] = m;
    }
}

// ---------------------------------------------------------------------------
// Counting sort of edges by receiver (CSR build)
// ---------------------------------------------------------------------------
__global__ void zero_counts_kernel(int n_nodes) {
    int i = blockIdx.x * blockDim.x + threadIdx.x;
    if (i < n_nodes) g_counts[i] = 0;
}

__global__ void hist_kernel(const int* __restrict__ receivers, int E) {
    int e = blockIdx.x * blockDim.x + threadIdx.x;
    if (e < E) atomicAdd(&g_counts[receivers[e]], 1);
}

// Single-block exclusive scan over n_nodes counts -> g_rowptr, g_cursor
__global__ void scan_kernel(int n_nodes) {
    __shared__ int ssum[1024];
    const int t = threadIdx.x;
    const int chunk = (n_nodes + 1023) / 1024;
    const int lo = t * chunk;
    const int hi = min(lo + chunk, n_nodes);
    int s = 0;
    for (int i = lo; i < hi; i++) s += g_counts[i];
    ssum[t] = s;
    __syncthreads();
    // Hillis-Steele inclusive scan
    for (int d = 1; d < 1024; d <<= 1) {
        int v = (t >= d) ? ssum[t - d] : 0;
        __syncthreads();
        ssum[t] += v;
        __syncthreads();
    }
    int base = (t == 0) ? 0 : ssum[t - 1];
    for (int i = lo; i < hi; i++) {
        int c = g_counts[i];
        g_rowptr[i] = base;
        g_cursor[i] = base;
        base += c;
    }
    if (t == 1023) g_rowptr[n_nodes] = ssum[1023];
}

__global__ void scatter_kernel(const int* __restrict__ receivers, int E) {
    int e = blockIdx.x * blockDim.x + threadIdx.x;
    if (e < E) {
        int pos = atomicAdd(&g_cursor[receivers[e]], 1);
        g_eids[pos] = e;
    }
}

// ---------------------------------------------------------------------------
// Aggregate: one warp per receiver node. Accumulate all incident edge
// messages in registers (lane l owns channel l), then one shared transpose
// and 8 coalesced 128B stores. Zero atomics, zero per-edge shared traffic.
// ---------------------------------------------------------------------------
__global__ void aggregate_kernel(const float* __restrict__ node_feats,
                                 const float4* __restrict__ edge_attrs,
                                 const int* __restrict__ senders,
                                 float* __restrict__ out,
                                 int n_nodes) {
    __shared__ float sh[8][OUT_ROW];               // 8 warps x 256 floats = 8 KB
    const int wid  = threadIdx.x >> 5;
    const int lane = threadIdx.x & 31;
    const int node = blockIdx.x * 8 + wid;
    if (node >= n_nodes) return;

    const int start = __ldg(&g_rowptr[node]);
    const int end   = __ldg(&g_rowptr[node + 1]);

    float a_s = 0.f, a_t = 0.f;
    float av0 = 0.f, av1 = 0.f, av2 = 0.f;
    float ap0 = 0.f, ap1 = 0.f, ap2 = 0.f;

    const float inv_dx = (float)(TABLE_N - 1) / (XMAX - XMIN);

    for (int i = start; i < end; i++) {
        const int e = __ldg(&g_eids[i]);
        const int s = __ldg(&senders[e]);
        const float4 ea = __ldg(&edge_attrs[e]);   // ea.x = ea0; (y,z,w) = ea1

        const float* nrow = node_feats + (size_t)s * NODE_ROW;
        const float s_e = __ldg(nrow + lane);
        const float v0  = __ldg(nrow + 32 + 3 * lane);
        const float v1  = __ldg(nrow + 33 + 3 * lane);
        const float v2  = __ldg(nrow + 34 + 3 * lane);

        float tt = (ea.x - XMIN) * inv_dx;
        tt = fminf(fmaxf(tt, 0.0f), (float)(TABLE_N - 1) - 1.0e-3f);
        const int i0 = (int)tt;
        const float f = tt - (float)i0;
        const float* row0 = g_mix_table + (size_t)i0 * 128;
        const float* row1 = row0 + 128;

        float a, b, m_s, m_t, m_v, m_p;
        a = __ldg(row0 + lane);       b = __ldg(row1 + lane);       m_s = fmaf(b - a, f, a);
        a = __ldg(row0 + 32 + lane);  b = __ldg(row1 + 32 + lane);  m_t = fmaf(b - a, f, a);
        a = __ldg(row0 + 64 + lane);  b = __ldg(row1 + 64 + lane);  m_v = fmaf(b - a, f, a);
        a = __ldg(row0 + 96 + lane);  b = __ldg(row1 + 96 + lane);  m_p = fmaf(b - a, f, a);

        a_s = fmaf(s_e, m_s, a_s);
        const float dot3 = fmaf(v0, ea.y, fmaf(v1, ea.z, v2 * ea.w));
        a_t = fmaf(dot3, m_t, a_t);                // INV_SQRT3 folded into table
        av0 = fmaf(v0, m_v, av0);
        av1 = fmaf(v1, m_v, av1);
        av2 = fmaf(v2, m_v, av2);
        const float sp = s_e * m_p;
        ap0 = fmaf(sp, ea.y, ap0);
        ap1 = fmaf(sp, ea.z, ap1);
        ap2 = fmaf(sp, ea.w, ap2);
    }

    // Transpose once per node via shared (stride-3 stores: conflict-free)
    float* shw = sh[wid];
    shw[lane]               = a_s;
    shw[32 + lane]          = a_t;
    shw[64  + 3 * lane]     = av0;
    shw[64  + 3 * lane + 1] = av1;
    shw[64  + 3 * lane + 2] = av2;
    shw[160 + 3 * lane]     = ap0;
    shw[160 + 3 * lane + 1] = ap1;
    shw[160 + 3 * lane + 2] = ap2;
    __syncwarp();

    float* op = out + (size_t)node * OUT_ROW;
#pragma unroll
    for (int j = 0; j < 8; j++)
        op[32 * j + lane] = shw[32 * j + lane];
}

// ---------------------------------------------------------------------------
// Launch
// inputs: 0 node_feats (50000x128 f32), 1 edge_attrs (800000x4 f32),
//         2 senders (int32), 3 receivers (int32),
//         4 w_mlp0 (1x64), 5 w_mlp1 (64x64), 6 w_mlp2 (64x128)
// output: 50000x256 f32
// ---------------------------------------------------------------------------
extern "C" void kernel_launch(void* const* d_in, const int* in_sizes, int n_in,
                              void* d_out, int out_size) {
    const float* node_feats = (const float*)d_in[0];
    const float* edge_attrs = (const float*)d_in[1];
    const int*   senders    = (const int*)d_in[2];
    const int*   receivers  = (const int*)d_in[3];
    const float* w0         = (const float*)d_in[4];
    const float* w1         = (const float*)d_in[5];
    const float* w2         = (const float*)d_in[6];
    float* out = (float*)d_out;
    const int E = in_sizes[1] / 4;          // edge_attrs is E x 4
    const int n_nodes = out_size / OUT_ROW; // output is n_nodes x 256

    build_table_kernel<<<TABLE_N, 128>>>(w0, w1, w2);
    zero_counts_kernel<<<(n_nodes + 255) / 256, 256>>>(n_nodes);
    hist_kernel<<<(E + 255) / 256, 256>>>(receivers, E);
    scan_kernel<<<1, 1024>>>(n_nodes);
    scatter_kernel<<<(E + 255) / 256, 256>>>(receivers, E);
    aggregate_kernel<<<(n_nodes + 7) / 8, 256>>>(node_feats,
                                                 (const float4*)edge_attrs,
                                                 senders, out, n_nodes);
}

// round 3
// speedup vs baseline: 2.1085x; 1.5049x over previous
#include <cuda_runtime.h>

#define N_NODES_MAX 50000
#define N_EDGES_MAX 800000
#define NODE_ROW 128          // 4*MUL floats per node
#define OUT_ROW 256           // output floats per node
#define TABLE_N 512
#define XMIN (-8.0f)
#define XMAX (8.0f)
#define INV_SQRT3 0.57735026918962576f
#define OUT_SCALE 0.25f       // 1/sqrt(16)
#define SCAN_B 1024
#define MAX_SCAN_BLOCKS 64

// ---- static device scratch (no allocations allowed) ----
__device__ float  g_mix_raw[TABLE_N * 128];        // raw mix values
__device__ float2 g_tab2[TABLE_N * 128];           // (value, slope) per entry
__device__ int    g_counts[N_NODES_MAX];
__device__ int    g_rowptr[N_NODES_MAX + 1];
__device__ int    g_cursor[N_NODES_MAX];
__device__ int    g_btot[MAX_SCAN_BLOCKS];
__device__ int    g_ssort[N_EDGES_MAX];            // senders sorted by receiver
__device__ float4 g_easort[N_EDGES_MAX];           // edge_attrs sorted by receiver

// ---------------------------------------------------------------------------
// Table build: mix(x) for TABLE_N grid points. One block per x.
// Folds: *0.25 global scale; cols [32,64) *= INV_SQRT3 (tp_0e factor).
// ---------------------------------------------------------------------------
__global__ void build_table_kernel(const float* __restrict__ w0,
                                   const float* __restrict__ w1,
                                   const float* __restrict__ w2) {
    __shared__ float h0[64];
    __shared__ float h1[64];
    const int t = threadIdx.x;                     // 0..127
    const float dx = (XMAX - XMIN) / (float)(TABLE_N - 1);
    const float x = XMIN + dx * (float)blockIdx.x;

    if (t < 64) {
        float z = x * w0[t];
        h0[t] = z / (1.0f + expf(-z));
    }
    __syncthreads();
    if (t < 64) {
        float acc = 0.0f;
#pragma unroll 8
        for (int i = 0; i < 64; i++) acc = fmaf(h0[i], w1[i * 64 + t], acc);
        float z = acc * 0.125f;
        h1[t] = z / (1.0f + expf(-z));
    }
    __syncthreads();
    {
        float acc = 0.0f;
#pragma unroll 8
        for (int i = 0; i < 64; i++) acc = fmaf(h1[i], w2[i * 128 + t], acc);
        float m = acc * 0.125f * OUT_SCALE;
        if (t >= 32 && t < 64) m *= INV_SQRT3;
        g_mix_raw[blockIdx.x * 128 + t] = m;
    }
}

// Pack (value, slope) pairs
__global__ void pack_table_kernel() {
    int i = blockIdx.x * blockDim.x + threadIdx.x;   // 0 .. TABLE_N*128-1
    if (i >= TABLE_N * 128) return;
    float v = g_mix_raw[i];
    float d = (i < (TABLE_N - 1) * 128) ? (g_mix_raw[i + 128] - v) : 0.0f;
    g_tab2[i] = make_float2(v, d);
}

// ---------------------------------------------------------------------------
// Counting sort of edges by receiver (CSR build) — fully parallel scan
// ---------------------------------------------------------------------------
__global__ void zero_counts_kernel(int n_nodes) {
    int i = blockIdx.x * blockDim.x + threadIdx.x;
    if (i < n_nodes) g_counts[i] = 0;
}

__global__ void hist_kernel(const int* __restrict__ receivers, int E) {
    int e = blockIdx.x * blockDim.x + threadIdx.x;
    if (e < E) atomicAdd(&g_counts[receivers[e]], 1);
}

// Phase 1: per-block exclusive scan of 1024 counts; block totals to g_btot
__global__ void scan1_kernel(int n_nodes) {
    __shared__ int s[SCAN_B];
    const int t = threadIdx.x;
    const int gid = blockIdx.x * SCAN_B + t;
    int v = (gid < n_nodes) ? g_counts[gid] : 0;
    s[t] = v;
    __syncthreads();
    for (int d = 1; d < SCAN_B; d <<= 1) {
        int x = (t >= d) ? s[t - d] : 0;
        __syncthreads();
        s[t] += x;
        __syncthreads();
    }
    if (gid < n_nodes) g_rowptr[gid] = s[t] - v;     // block-local exclusive
    if (t == SCAN_B - 1) g_btot[blockIdx.x] = s[t];
}

// Phase 2: exclusive scan of block totals (<= 64 blocks), single small block
__global__ void scan2_kernel(int nb) {
    __shared__ int s[MAX_SCAN_BLOCKS];
    const int t = threadIdx.x;
    int v = (t < nb) ? g_btot[t] : 0;
    s[t] = v;
    __syncthreads();
    for (int d = 1; d < MAX_SCAN_BLOCKS; d <<= 1) {
        int x = (t >= d) ? s[t - d] : 0;
        __syncthreads();
        s[t] += x;
        __syncthreads();
    }
    if (t < nb) g_btot[t] = s[t] - v;                // exclusive
}

// Phase 3: add block offsets; init cursor; cap rowptr
__global__ void scan3_kernel(int n_nodes, int E) {
    int gid = blockIdx.x * blockDim.x + threadIdx.x;
    if (gid < n_nodes) {
        int r = g_rowptr[gid] + g_btot[gid >> 10];
        g_rowptr[gid] = r;
        g_cursor[gid] = r;
    }
    if (gid == 0) g_rowptr[n_nodes] = E;
}

// Scatter: sort the *payload* (sender id + edge attrs), not indices.
// Reads coalesced; writes random but no-return.
__global__ void scatter_kernel(const int* __restrict__ senders,
                               const int* __restrict__ receivers,
                               const float4* __restrict__ edge_attrs,
                               int E) {
    int e = blockIdx.x * blockDim.x + threadIdx.x;
    if (e < E) {
        int pos = atomicAdd(&g_cursor[receivers[e]], 1);
        g_ssort[pos]  = senders[e];
        g_easort[pos] = edge_attrs[e];
    }
}

// ---------------------------------------------------------------------------
// Aggregate: one warp per receiver node. Lane l owns channel l. Register
// accumulation over the node's incident edges, one shared transpose, 8
// coalesced 128B stores. Zero atomics.
// ---------------------------------------------------------------------------
__global__ void aggregate_kernel(const float* __restrict__ node_feats,
                                 float* __restrict__ out,
                                 int n_nodes) {
    __shared__ float sh[8][OUT_ROW];               // 8 warps x 256 floats = 8 KB
    const int wid  = threadIdx.x >> 5;
    const int lane = threadIdx.x & 31;
    const int node = blockIdx.x * 8 + wid;
    if (node >= n_nodes) return;

    const int start = __ldg(&g_rowptr[node]);
    const int end   = __ldg(&g_rowptr[node + 1]);

    float a_s = 0.f, a_t = 0.f;
    float av0 = 0.f, av1 = 0.f, av2 = 0.f;
    float ap0 = 0.f, ap1 = 0.f, ap2 = 0.f;

    const float inv_dx = (float)(TABLE_N - 1) / (XMAX - XMIN);

    for (int i = start; i < end; i++) {
        const int s = __ldg(&g_ssort[i]);
        const float4 ea = __ldg(&g_easort[i]);     // ea.x = ea0; (y,z,w) = ea1

        const float* nrow = node_feats + (size_t)s * NODE_ROW;
        const float s_e = __ldg(nrow + lane);
        const float v0  = __ldg(nrow + 32 + 3 * lane);
        const float v1  = __ldg(nrow + 33 + 3 * lane);
        const float v2  = __ldg(nrow + 34 + 3 * lane);

        float tt = (ea.x - XMIN) * inv_dx;
        tt = fminf(fmaxf(tt, 0.0f), (float)(TABLE_N - 1) - 1.0e-3f);
        const int i0 = (int)tt;
        const float f = tt - (float)i0;
        const float2* row = g_tab2 + (size_t)i0 * 128;

        float2 p;
        p = __ldg(row + lane);        const float m_s = fmaf(p.y, f, p.x);
        p = __ldg(row + 32 + lane);   const float m_t = fmaf(p.y, f, p.x);
        p = __ldg(row + 64 + lane);   const float m_v = fmaf(p.y, f, p.x);
        p = __ldg(row + 96 + lane);   const float m_p = fmaf(p.y, f, p.x);

        a_s = fmaf(s_e, m_s, a_s);
        const float dot3 = fmaf(v0, ea.y, fmaf(v1, ea.z, v2 * ea.w));
        a_t = fmaf(dot3, m_t, a_t);                // INV_SQRT3 folded into table
        av0 = fmaf(v0, m_v, av0);
        av1 = fmaf(v1, m_v, av1);
        av2 = fmaf(v2, m_v, av2);
        const float sp = s_e * m_p;
        ap0 = fmaf(sp, ea.y, ap0);
        ap1 = fmaf(sp, ea.z, ap1);
        ap2 = fmaf(sp, ea.w, ap2);
    }

    // Transpose once per node via shared (stride-3 stores: conflict-free)
    float* shw = sh[wid];
    shw[lane]               = a_s;
    shw[32 + lane]          = a_t;
    shw[64  + 3 * lane]     = av0;
    shw[64  + 3 * lane + 1] = av1;
    shw[64  + 3 * lane + 2] = av2;
    shw[160 + 3 * lane]     = ap0;
    shw[160 + 3 * lane + 1] = ap1;
    shw[160 + 3 * lane + 2] = ap2;
    __syncwarp();

    float* op = out + (size_t)node * OUT_ROW;
#pragma unroll
    for (int j = 0; j < 8; j++)
        op[32 * j + lane] = shw[32 * j + lane];
}

// ---------------------------------------------------------------------------
// Launch
// inputs: 0 node_feats (50000x128 f32), 1 edge_attrs (800000x4 f32),
//         2 senders (int32), 3 receivers (int32),
//         4 w_mlp0 (1x64), 5 w_mlp1 (64x64), 6 w_mlp2 (64x128)
// output: 50000x256 f32
// ---------------------------------------------------------------------------
extern "C" void kernel_launch(void* const* d_in, const int* in_sizes, int n_in,
                              void* d_out, int out_size) {
    const float* node_feats = (const float*)d_in[0];
    const float* edge_attrs = (const float*)d_in[1];
    const int*   senders    = (const int*)d_in[2];
    const int*   receivers  = (const int*)d_in[3];
    const float* w0         = (const float*)d_in[4];
    const float* w1         = (const float*)d_in[5];
    const float* w2         = (const float*)d_in[6];
    float* out = (float*)d_out;
    const int E = in_sizes[1] / 4;          // edge_attrs is E x 4
    const int n_nodes = out_size / OUT_ROW; // output is n_nodes x 256
    const int nb = (n_nodes + SCAN_B - 1) / SCAN_B;   // <= 64

    build_table_kernel<<<TABLE_N, 128>>>(w0, w1, w2);
    pack_table_kernel<<<(TABLE_N * 128 + 255) / 256, 256>>>();
    zero_counts_kernel<<<(n_nodes + 255) / 256, 256>>>(n_nodes);
    hist_kernel<<<(E + 255) / 256, 256>>>(receivers, E);
    scan1_kernel<<<nb, SCAN_B>>>(n_nodes);
    scan2_kernel<<<1, MAX_SCAN_BLOCKS>>>(nb);
    scan3_kernel<<<(n_nodes + 255) / 256, 256>>>(n_nodes, E);
    scatter_kernel<<<(E + 255) / 256, 256>>>(senders, receivers,
                                             (const float4*)edge_attrs, E);
    aggregate_kernel<<<(n_nodes + 7) / 8, 256>>>(node_feats, out, n_nodes);
}